// round 8
// baseline (speedup 1.0000x reference)
#include <cuda_runtime.h>
#include <math.h>
#include <stdint.h>

// Problem constants: B=8, S=1024, D=1024, H=16, hd=64
#define NB 8
#define NS 1024
#define ND 1024
#define NH 16
#define HD 64

// Scratch (allocation-free rule: __device__ globals)
__device__ float g_Q[NB * NH * NS * HD];   // [B,H,S,hd]
__device__ float g_K[NB * NH * NS * HD];
__device__ float g_V[NB * NH * NS * HD];
__device__ float g_ctx[NB * NS * ND];      // [B,S,D]

// tf32 lives in a b32 container: cvt dst must be a .b32 register.
__device__ __forceinline__ uint32_t to_tf32(float x) {
    uint32_t r;
    asm("cvt.rna.tf32.f32 %0, %1;" : "=r"(r) : "f"(x));
    return r;
}

__device__ __forceinline__ void mma_tf32(float c[4], const uint32_t a[4], const uint32_t b[2]) {
    asm volatile(
        "mma.sync.aligned.m16n8k8.row.col.f32.tf32.tf32.f32 "
        "{%0,%1,%2,%3}, {%4,%5,%6,%7}, {%8,%9}, {%0,%1,%2,%3};"
        : "+f"(c[0]), "+f"(c[1]), "+f"(c[2]), "+f"(c[3])
        : "r"(a[0]), "r"(a[1]), "r"(a[2]), "r"(a[3]), "r"(b[0]), "r"(b[1]));
}

// ---------------------------------------------------------------------------
// tf32 tensor-core GEMM with FRAGMENT-MAJOR smem layout, double-buffered.
// BM=BN=128, BK=32, 256 threads = 8 warps (2 x 4), warp tile 64x32.
//
// A is stored pre-arranged in m16n8k8 A-fragment order:
//   element (m, k) -> Afrag[(ks*8 + tm)*128 + lane*4 + reg]
//     ks = k>>3, tm = m>>4, lane = (m&7)*4 + (k&3),
//     reg = ((k>>2)&1)*2 + ((m>>3)&1)
//   compute side: ONE LDS.128 per (ks, m-tile) gives {a0,a1,a2,a3}. Conflict-free.
// B likewise in B-fragment order:
//   element (n, k) -> Bfrag[(ks*16 + tn)*64 + lane*2 + reg]
//     tn = n>>3, lane = (n&7)*4 + (k&3), reg = (k>>2)&1
//   compute side: ONE LDS.64 per (ks, n-tile) gives {b0,b1}. Conflict-free.
// ---------------------------------------------------------------------------
#define A_FRAG_U32 (4 * 8 * 128)     // 4096 words per buffer
#define B_FRAG_U32 (4 * 16 * 64)     // 4096 words per buffer
#define GEMM_SMEM_BYTES ((2 * A_FRAG_U32 + 2 * B_FRAG_U32) * 4)  // 65536

template <int MODE>
__global__ __launch_bounds__(256) void gemm_tf32(
    const float* __restrict__ A, const float* __restrict__ Bw,
    const float* __restrict__ bias, float* __restrict__ out,
    int K, int N)
{
    extern __shared__ uint32_t dynsh[];
    uint32_t* Asm = dynsh;                       // [buf][A_FRAG_U32]
    uint32_t* Bsm = dynsh + 2 * A_FRAG_U32;      // [buf][B_FRAG_U32]

    const int tid  = threadIdx.x;
    const int lane = tid & 31;
    const int warp = tid >> 5;
    const int g    = lane >> 2;      // groupID 0..7
    const int tig  = lane & 3;       // thread in group 0..3
    const int wm0 = (warp >> 2) * 64;
    const int wn0 = (warp & 3) * 32;
    const int wtm = (warp >> 2) * 4; // warp's m-tile base (of 8)
    const int wtn = (warp & 3) * 4;  // warp's n-tile base (of 16)

    const int m0 = blockIdx.y * 128;
    const int n0 = blockIdx.x * 128;

    const float* Ap = (MODE == 2) ? (const float*)g_ctx : A;

    const int ra = tid >> 3;         // 0..31  (A row base, +32 per l)
    const int kc = (tid & 7) * 4;    // 0..28  (A k column base)
    const int kr0 = tid >> 5;        // 0..7   (B k row base, +8 per l)
    const int nb4 = (tid & 31) * 4;  // 0..124 (B n column base)

    const float* Aldg = Ap + (size_t)(m0 + ra) * K + kc;
    const float* Bldg = Bw + (size_t)kr0 * N + n0 + nb4;

    // Precomputed fragment-store bases (constant across k0 iterations):
    // A: per l, m = ra + 32*l, k = kc..kc+3
    const int ks_a  = kc >> 3;
    const int rega_hi = ((kc >> 2) & 1) << 1;
    uint32_t a_base[4];
#pragma unroll
    for (int l = 0; l < 4; l++) {
        const int m = ra + 32 * l;
        a_base[l] = (uint32_t)(((ks_a * 8 + (m >> 4)) << 7)
                               + ((m & 7) << 4) + rega_hi + ((m >> 3) & 1));
    }
    // B: per l, k = kr0 + 8*l (ks = l), n = nb4..nb4+3
    const int tn_b  = nb4 >> 3;
    const int regb  = (kr0 >> 2) & 1;
    const int tigb2 = (kr0 & 3) << 1;
    uint32_t b_base[4];
#pragma unroll
    for (int l = 0; l < 4; l++) {
        b_base[l] = (uint32_t)(((l * 16 + tn_b) << 6)
                               + ((nb4 & 7) << 3) + tigb2 + regb);
    }

    float acc[4][4][4];
#pragma unroll
    for (int mt = 0; mt < 4; mt++)
#pragma unroll
        for (int nt = 0; nt < 4; nt++)
#pragma unroll
            for (int e = 0; e < 4; e++) acc[mt][nt][e] = 0.0f;

    float4 pa[4], pb[4];

    // Prologue: load + store tile 0 into buf 0
#pragma unroll
    for (int l = 0; l < 4; l++) {
        pa[l] = *(const float4*)(Aldg + (size_t)(l * 32) * K);
        pb[l] = *(const float4*)(Bldg + (size_t)(l * 8) * N);
    }
#pragma unroll
    for (int l = 0; l < 4; l++) {
        Asm[a_base[l] + 0]  = to_tf32(pa[l].x);
        Asm[a_base[l] + 4]  = to_tf32(pa[l].y);
        Asm[a_base[l] + 8]  = to_tf32(pa[l].z);
        Asm[a_base[l] + 12] = to_tf32(pa[l].w);
        Bsm[b_base[l] + 0]  = to_tf32(pb[l].x);
        Bsm[b_base[l] + 8]  = to_tf32(pb[l].y);
        Bsm[b_base[l] + 16] = to_tf32(pb[l].z);
        Bsm[b_base[l] + 24] = to_tf32(pb[l].w);
    }
    __syncthreads();

    int buf = 0;
    for (int k0 = 0; k0 < K; k0 += 32) {
        const bool more = (k0 + 32 < K);
        if (more) {
#pragma unroll
            for (int l = 0; l < 4; l++) {
                pa[l] = *(const float4*)(Aldg + (size_t)(l * 32) * K + (k0 + 32));
                pb[l] = *(const float4*)(Bldg + (size_t)((k0 + 32) + l * 8) * N);
            }
        }

        const uint32_t* Ab = Asm + buf * A_FRAG_U32;
        const uint32_t* Bb = Bsm + buf * B_FRAG_U32;
#pragma unroll
        for (int ks = 0; ks < 4; ks++) {
            uint4 afv[4];
            uint2 bfv[4];
#pragma unroll
            for (int mt = 0; mt < 4; mt++)
                afv[mt] = *(const uint4*)(Ab + (((ks * 8 + wtm + mt) << 7) + lane * 4));
#pragma unroll
            for (int nt = 0; nt < 4; nt++)
                bfv[nt] = *(const uint2*)(Bb + (((ks * 16 + wtn + nt) << 6) + lane * 2));
#pragma unroll
            for (int mt = 0; mt < 4; mt++) {
                const uint32_t af[4] = {afv[mt].x, afv[mt].y, afv[mt].z, afv[mt].w};
#pragma unroll
                for (int nt = 0; nt < 4; nt++) {
                    const uint32_t bf[2] = {bfv[nt].x, bfv[nt].y};
                    mma_tf32(acc[mt][nt], af, bf);
                }
            }
        }

        if (more) {
            uint32_t* An = Asm + (buf ^ 1) * A_FRAG_U32;
            uint32_t* Bn = Bsm + (buf ^ 1) * B_FRAG_U32;
#pragma unroll
            for (int l = 0; l < 4; l++) {
                An[a_base[l] + 0]  = to_tf32(pa[l].x);
                An[a_base[l] + 4]  = to_tf32(pa[l].y);
                An[a_base[l] + 8]  = to_tf32(pa[l].z);
                An[a_base[l] + 12] = to_tf32(pa[l].w);
                Bn[b_base[l] + 0]  = to_tf32(pb[l].x);
                Bn[b_base[l] + 8]  = to_tf32(pb[l].y);
                Bn[b_base[l] + 16] = to_tf32(pb[l].z);
                Bn[b_base[l] + 24] = to_tf32(pb[l].w);
            }
            __syncthreads();
            buf ^= 1;
        }
    }

    // Epilogue: c-fragment (mt,nt) covers rows {r0, r0+8}, cols {c0, c0+1}
#pragma unroll
    for (int mt = 0; mt < 4; mt++) {
        const int rbase = m0 + wm0 + mt * 16 + g;
#pragma unroll
        for (int nt = 0; nt < 4; nt++) {
            const int cbase = n0 + wn0 + nt * 8 + tig * 2;
#pragma unroll
            for (int e = 0; e < 4; e++) {
                const int r = rbase + (e >> 1) * 8;
                const int c = cbase + (e & 1);
                const float val = acc[mt][nt][e] + bias[c];
                const int b = r >> 10;
                const int s = r & 1023;
                if (MODE == 0) {
                    const int h = c >> 7;
                    const int w = c & 127;
                    if (w < 64)
                        g_Q[(((size_t)(b * NH + h)) * NS + s) * HD + w] = val;
                    else
                        g_K[(((size_t)(b * NH + h)) * NS + s) * HD + (w - 64)] = val;
                } else if (MODE == 1) {
                    const int h = c >> 6;
                    const int d = c & 63;
                    g_V[(((size_t)(b * NH + h)) * NS + s) * HD + d] = val;
                } else {
                    out[(size_t)r * N + c] = val;
                }
            }
        }
    }
}

// ---------------------------------------------------------------------------
// Flash attention on tensor cores (tf32 mma.m16n8k8). Unchanged from R7 pass.
// ---------------------------------------------------------------------------
#define QS_STR 68
#define KS_STR 68
#define VS_STR 72
#define PS_STR 68
#define QS_OFF 0
#define KS_OFF (64 * QS_STR)                       // 4352
#define VS_OFF (KS_OFF + 64 * KS_STR)              // 8704
#define PS_OFF (VS_OFF + 64 * VS_STR)              // 13312
#define ATTN_SMEM_U32 (PS_OFF + 64 * PS_STR)       // 17664
#define ATTN_SMEM_BYTES (ATTN_SMEM_U32 * 4)        // 70656

__global__ __launch_bounds__(128) void attn_kernel()
{
    extern __shared__ uint32_t sh[];
    uint32_t* Qs = sh + QS_OFF;   // [row][d]   stride 68
    uint32_t* Ks = sh + KS_OFF;   // [seq][d]   stride 68
    uint32_t* Vs = sh + VS_OFF;   // [seq][d]   stride 72
    uint32_t* Ps = sh + PS_OFF;   // [row][seq] stride 68

    const int tid  = threadIdx.x;
    const int lane = tid & 31;
    const int warp = tid >> 5;          // 0..3
    const int g    = lane >> 2;         // 0..7
    const int tig  = lane & 3;          // 0..3
    const int wrow = warp * 16;         // warp's Q-row base within tile

    const int qt = blockIdx.x;          // 0..15 q tile
    const int bh = blockIdx.y;          // 0..127

    const float* Qg  = g_Q + ((size_t)bh * NS + qt * 64) * HD;
    const float* Kg0 = g_K + (size_t)bh * NS * HD;
    const float* Vg0 = g_V + (size_t)bh * NS * HD;

    // Load Q tile once: fold softmax scale 0.125, convert to tf32.
    for (int f = tid; f < 1024; f += 128) {          // 1024 float4
        const int row = f >> 4;
        const int d4  = (f & 15) << 2;
        float4 v = *(const float4*)(Qg + row * HD + d4);
        uint4 t;
        t.x = to_tf32(v.x * 0.125f); t.y = to_tf32(v.y * 0.125f);
        t.z = to_tf32(v.z * 0.125f); t.w = to_tf32(v.w * 0.125f);
        *(uint4*)(&Qs[row * QS_STR + d4]) = t;
    }

    float oacc[8][4];                    // [d-tile][frag]
#pragma unroll
    for (int nt = 0; nt < 8; nt++)
#pragma unroll
        for (int e = 0; e < 4; e++) oacc[nt][e] = 0.0f;
    float M0 = -1e30f, M1 = -1e30f, L0 = 0.0f, L1 = 0.0f;

    for (int kt = 0; kt < 16; kt++) {
        const float* Kg = Kg0 + (size_t)kt * 64 * HD;
        const float* Vg = Vg0 + (size_t)kt * 64 * HD;
        __syncthreads();                 // protect Ks/Vs from previous iter readers
        for (int f = tid; f < 1024; f += 128) {
            const int row = f >> 4;
            const int d4  = (f & 15) << 2;
            float4 kv = *(const float4*)(Kg + row * HD + d4);
            float4 vv = *(const float4*)(Vg + row * HD + d4);
            uint4 tk, tv;
            tk.x = to_tf32(kv.x); tk.y = to_tf32(kv.y);
            tk.z = to_tf32(kv.z); tk.w = to_tf32(kv.w);
            tv.x = to_tf32(vv.x); tv.y = to_tf32(vv.y);
            tv.z = to_tf32(vv.z); tv.w = to_tf32(vv.w);
            *(uint4*)(&Ks[row * KS_STR + d4]) = tk;
            *(uint4*)(&Vs[row * VS_STR + d4]) = tv;
        }
        __syncthreads();

        // ---- S = Q @ K^T : 16x64 per warp, k over d (8 steps) ----
        float sacc[8][4];
#pragma unroll
        for (int nt = 0; nt < 8; nt++)
#pragma unroll
            for (int e = 0; e < 4; e++) sacc[nt][e] = 0.0f;

#pragma unroll
        for (int ks = 0; ks < 8; ks++) {
            const int k8 = ks * 8;
            uint32_t af[4];
            af[0] = Qs[(wrow + g)     * QS_STR + k8 + tig];
            af[1] = Qs[(wrow + g + 8) * QS_STR + k8 + tig];
            af[2] = Qs[(wrow + g)     * QS_STR + k8 + tig + 4];
            af[3] = Qs[(wrow + g + 8) * QS_STR + k8 + tig + 4];
#pragma unroll
            for (int nt = 0; nt < 8; nt++) {
                uint32_t bf[2];
                bf[0] = Ks[(nt * 8 + g) * KS_STR + k8 + tig];
                bf[1] = Ks[(nt * 8 + g) * KS_STR + k8 + tig + 4];
                mma_tf32(sacc[nt], af, bf);
            }
        }

        // ---- online softmax on fragments (rows g and g+8) ----
        float rm0 = -1e30f, rm1 = -1e30f;
#pragma unroll
        for (int nt = 0; nt < 8; nt++) {
            rm0 = fmaxf(rm0, fmaxf(sacc[nt][0], sacc[nt][1]));
            rm1 = fmaxf(rm1, fmaxf(sacc[nt][2], sacc[nt][3]));
        }
        rm0 = fmaxf(rm0, __shfl_xor_sync(0xffffffffu, rm0, 1));
        rm0 = fmaxf(rm0, __shfl_xor_sync(0xffffffffu, rm0, 2));
        rm1 = fmaxf(rm1, __shfl_xor_sync(0xffffffffu, rm1, 1));
        rm1 = fmaxf(rm1, __shfl_xor_sync(0xffffffffu, rm1, 2));

        const float mn0 = fmaxf(M0, rm0);
        const float mn1 = fmaxf(M1, rm1);
        const float fac0 = __expf(M0 - mn0);
        const float fac1 = __expf(M1 - mn1);
        float rs0 = 0.0f, rs1 = 0.0f;
#pragma unroll
        for (int nt = 0; nt < 8; nt++) {
            float p0 = __expf(sacc[nt][0] - mn0);
            float p1 = __expf(sacc[nt][1] - mn0);
            float p2 = __expf(sacc[nt][2] - mn1);
            float p3 = __expf(sacc[nt][3] - mn1);
            rs0 += p0 + p1;
            rs1 += p2 + p3;
            uint2 u0, u1;
            u0.x = to_tf32(p0); u0.y = to_tf32(p1);
            u1.x = to_tf32(p2); u1.y = to_tf32(p3);
            *(uint2*)(&Ps[(wrow + g)     * PS_STR + nt * 8 + 2 * tig]) = u0;
            *(uint2*)(&Ps[(wrow + g + 8) * PS_STR + nt * 8 + 2 * tig]) = u1;
        }
        rs0 += __shfl_xor_sync(0xffffffffu, rs0, 1);
        rs0 += __shfl_xor_sync(0xffffffffu, rs0, 2);
        rs1 += __shfl_xor_sync(0xffffffffu, rs1, 1);
        rs1 += __shfl_xor_sync(0xffffffffu, rs1, 2);
        L0 = L0 * fac0 + rs0;
        L1 = L1 * fac1 + rs1;
        M0 = mn0; M1 = mn1;
#pragma unroll
        for (int nt = 0; nt < 8; nt++) {
            oacc[nt][0] *= fac0; oacc[nt][1] *= fac0;
            oacc[nt][2] *= fac1; oacc[nt][3] *= fac1;
        }
        __syncwarp();                   // Ps region is per-warp; warp-fence enough

        // ---- O += P @ V : k over keys (8 steps), n over d (8 tiles) ----
#pragma unroll
        for (int ks = 0; ks < 8; ks++) {
            const int k8 = ks * 8;
            uint32_t af[4];
            af[0] = Ps[(wrow + g)     * PS_STR + k8 + tig];
            af[1] = Ps[(wrow + g + 8) * PS_STR + k8 + tig];
            af[2] = Ps[(wrow + g)     * PS_STR + k8 + tig + 4];
            af[3] = Ps[(wrow + g + 8) * PS_STR + k8 + tig + 4];
#pragma unroll
            for (int nt = 0; nt < 8; nt++) {
                uint32_t bf[2];
                bf[0] = Vs[(k8 + tig)     * VS_STR + nt * 8 + g];
                bf[1] = Vs[(k8 + tig + 4) * VS_STR + nt * 8 + g];
                mma_tf32(oacc[nt], af, bf);
            }
        }
        __syncwarp();                   // done reading Ps before next overwrite
    }

    // Finalize: divide by L, write ctx [B,S,D]  (D col = h*64 + d)
    const int b = bh >> 4;
    const int h = bh & 15;
    const float inv0 = 1.0f / L0;
    const float inv1 = 1.0f / L1;
    const int sr0 = qt * 64 + wrow + g;
    float* out0 = g_ctx + ((size_t)(b * NS + sr0))     * ND + h * HD;
    float* out1 = g_ctx + ((size_t)(b * NS + sr0 + 8)) * ND + h * HD;
#pragma unroll
    for (int nt = 0; nt < 8; nt++) {
        const int c = nt * 8 + 2 * tig;
        *(float2*)(out0 + c) = make_float2(oacc[nt][0] * inv0, oacc[nt][1] * inv0);
        *(float2*)(out1 + c) = make_float2(oacc[nt][2] * inv1, oacc[nt][3] * inv1);
    }
}

// ---------------------------------------------------------------------------
extern "C" void kernel_launch(void* const* d_in, const int* in_sizes, int n_in,
                              void* d_out, int out_size)
{
    const float* in_q = (const float*)d_in[0];
    const float* enc  = (const float*)d_in[1];
    const float* Wqk  = (const float*)d_in[2];
    const float* bqk  = (const float*)d_in[3];
    const float* Wv   = (const float*)d_in[4];
    const float* bv   = (const float*)d_in[5];
    const float* Wo   = (const float*)d_in[6];
    const float* bo   = (const float*)d_in[7];
    float* out = (float*)d_out;

    cudaFuncSetAttribute(gemm_tf32<0>,
                         cudaFuncAttributeMaxDynamicSharedMemorySize,
                         GEMM_SMEM_BYTES);
    cudaFuncSetAttribute(gemm_tf32<1>,
                         cudaFuncAttributeMaxDynamicSharedMemorySize,
                         GEMM_SMEM_BYTES);
    cudaFuncSetAttribute(gemm_tf32<2>,
                         cudaFuncAttributeMaxDynamicSharedMemorySize,
                         GEMM_SMEM_BYTES);
    cudaFuncSetAttribute(attn_kernel,
                         cudaFuncAttributeMaxDynamicSharedMemorySize,
                         ATTN_SMEM_BYTES);

    gemm_tf32<0><<<dim3(2048 / 128, 8192 / 128), 256, GEMM_SMEM_BYTES>>>(enc, Wqk, bqk, nullptr, 1024, 2048);
    gemm_tf32<1><<<dim3(1024 / 128, 8192 / 128), 256, GEMM_SMEM_BYTES>>>(in_q, Wv, bv, nullptr, 1024, 1024);
    attn_kernel<<<dim3(16, 128), 128, ATTN_SMEM_BYTES>>>();
    gemm_tf32<2><<<dim3(1024 / 128, 8192 / 128), 256, GEMM_SMEM_BYTES>>>(nullptr, Wo, bo, out, 1024, 1024);
}

// round 9
// speedup vs baseline: 2.2960x; 2.2960x over previous
#include <cuda_runtime.h>
#include <math.h>
#include <stdint.h>

// Problem constants: B=8, S=1024, D=1024, H=16, hd=64
#define NB 8
#define NS 1024
#define ND 1024
#define NH 16
#define HD 64

// Scratch (allocation-free rule: __device__ globals)
__device__ float g_Q[NB * NH * NS * HD];   // [B,H,S,hd]
__device__ float g_K[NB * NH * NS * HD];
__device__ float g_V[NB * NH * NS * HD];
__device__ float g_ctx[NB * NS * ND];      // [B,S,D]

// tf32 lives in a b32 container: cvt dst must be a .b32 register.
__device__ __forceinline__ uint32_t to_tf32(float x) {
    uint32_t r;
    asm("cvt.rna.tf32.f32 %0, %1;" : "=r"(r) : "f"(x));
    return r;
}

__device__ __forceinline__ void mma_tf32(float c[4], const uint32_t a[4], const uint32_t b[2]) {
    asm volatile(
        "mma.sync.aligned.m16n8k8.row.col.f32.tf32.tf32.f32 "
        "{%0,%1,%2,%3}, {%4,%5,%6,%7}, {%8,%9}, {%0,%1,%2,%3};"
        : "+f"(c[0]), "+f"(c[1]), "+f"(c[2]), "+f"(c[3])
        : "r"(a[0]), "r"(a[1]), "r"(a[2]), "r"(a[3]), "r"(b[0]), "r"(b[1]));
}

__device__ __forceinline__ void ldsm_x4(uint4& d, uint32_t saddr) {
    asm volatile("ldmatrix.sync.aligned.m8n8.x4.shared.b16 {%0,%1,%2,%3}, [%4];"
        : "=r"(d.x), "=r"(d.y), "=r"(d.z), "=r"(d.w) : "r"(saddr));
}
__device__ __forceinline__ void ldsm_x2(uint2& d, uint32_t saddr) {
    asm volatile("ldmatrix.sync.aligned.m8n8.x2.shared.b16 {%0,%1}, [%2];"
        : "=r"(d.x), "=r"(d.y) : "r"(saddr));
}

// ---------------------------------------------------------------------------
// tf32 GEMM with ldmatrix + conflict-free padded layout, double-buffered.
// BM=BN=128, BK=32, 256 threads = 8 warps (2 x 4), warp tile 64x32.
// SMEM unit (16B) = 4 consecutive tf32 of one row (m or n) within a k-quad:
//   byte_off(ks, row, h) = ks*6176 + row*48 + h*16    (ks = k>>3, h = (k>>2)&1)
// Row stride 48B  -> LDSM 8-row fetch banks = 3*l mod 8 (permutation).
// ks  stride 6176B (386 units == 2 mod 8) -> A-store phase banks = 2ks+h (perm).
// ---------------------------------------------------------------------------
#define KSBLK_BYTES 6176                     // 386 units * 16B
#define MAT_BUF_BYTES (4 * KSBLK_BYTES)      // 24704 per matrix per buffer
#define BUF_STRIDE (2 * MAT_BUF_BYTES)       // 49408 (A then B)
#define GEMM_SMEM_BYTES (2 * BUF_STRIDE)     // 98816

template <int MODE>
__global__ __launch_bounds__(256) void gemm_tf32(
    const float* __restrict__ A, const float* __restrict__ Bw,
    const float* __restrict__ bias, float* __restrict__ out,
    int K, int N)
{
    extern __shared__ uint32_t dynsh[];
    char* smem_c = (char*)dynsh;
    const uint32_t smem_s = (uint32_t)__cvta_generic_to_shared(dynsh);

    const int tid  = threadIdx.x;
    const int lane = tid & 31;
    const int warp = tid >> 5;
    const int g    = lane >> 2;
    const int tig  = lane & 3;
    const int wm0 = (warp >> 2) * 64;
    const int wn0 = (warp & 3) * 32;

    const int m0 = blockIdx.y * 128;
    const int n0 = blockIdx.x * 128;

    const float* Ap = (MODE == 2) ? (const float*)g_ctx : A;

    // ---- A global loads: 4x LDG.128, row-chunk coalesced (as R7) ----
    const int ra = tid >> 3;          // m row base (+32 per l)
    const int kc = (tid & 7) * 4;     // k quad base
    const float* Aldg = Ap + (size_t)(m0 + ra) * K + kc;

    // ---- B global loads: 16x LDG.32, lanes span consecutive n (coalesced) ----
    const int nB = tid & 127;         // n column owned by this thread
    const int qb = (tid >> 7) * 4;    // k-quad base (0 or 4); unit q = qb+l
    const float* Bldg = Bw + n0 + nB;

    // ---- smem store byte offsets (within a matrix buffer) ----
    const int ksA = kc >> 3, hA = (kc >> 2) & 1;
    uint32_t a_sts[4], b_sts[4];
#pragma unroll
    for (int l = 0; l < 4; l++) {
        const int m = ra + 32 * l;
        a_sts[l] = (uint32_t)(ksA * KSBLK_BYTES + m * 48 + hA * 16);
        const int q = qb + l;
        b_sts[l] = (uint32_t)((q >> 1) * KSBLK_BYTES + nB * 48 + (q & 1) * 16);
    }

    // ---- LDSM per-lane read offsets (add buf + ks*6176 at use) ----
    uint32_t a_ld[4], b_ld[4];
    {
        const int rl   = ((lane >> 3) & 1) * 8 + (lane & 7);
        const int hsel = lane >> 4;
#pragma unroll
        for (int mt = 0; mt < 4; mt++)
            a_ld[mt] = (uint32_t)((wm0 + mt * 16 + rl) * 48 + hsel * 16);
        const int nl    = lane & 7;
        const int hsel2 = (lane >> 3) & 1;
#pragma unroll
        for (int nt = 0; nt < 4; nt++)
            b_ld[nt] = (uint32_t)((wn0 + nt * 8 + nl) * 48 + hsel2 * 16);
    }

    float acc[4][4][4];
#pragma unroll
    for (int mt = 0; mt < 4; mt++)
#pragma unroll
        for (int nt = 0; nt < 4; nt++)
#pragma unroll
            for (int e = 0; e < 4; e++) acc[mt][nt][e] = 0.0f;

    float4 pa[4];
    float  bv[4][4];

    // Prologue: load tile 0
#pragma unroll
    for (int l = 0; l < 4; l++) {
        pa[l] = *(const float4*)(Aldg + (size_t)(l * 32) * K);
#pragma unroll
        for (int i = 0; i < 4; i++)
            bv[l][i] = Bldg[(size_t)(4 * (qb + l) + i) * N];
    }
    // Store tile 0 -> buf 0
    {
        char* ab = smem_c;
        char* bb = smem_c + MAT_BUF_BYTES;
#pragma unroll
        for (int l = 0; l < 4; l++) {
            uint4 ta;
            ta.x = to_tf32(pa[l].x); ta.y = to_tf32(pa[l].y);
            ta.z = to_tf32(pa[l].z); ta.w = to_tf32(pa[l].w);
            *(uint4*)(ab + a_sts[l]) = ta;
            uint4 tb;
            tb.x = to_tf32(bv[l][0]); tb.y = to_tf32(bv[l][1]);
            tb.z = to_tf32(bv[l][2]); tb.w = to_tf32(bv[l][3]);
            *(uint4*)(bb + b_sts[l]) = tb;
        }
    }
    __syncthreads();

    int buf = 0;
    for (int k0 = 0; k0 < K; k0 += 32) {
        const bool more = (k0 + 32 < K);
        if (more) {
#pragma unroll
            for (int l = 0; l < 4; l++) {
                pa[l] = *(const float4*)(Aldg + (size_t)(l * 32) * K + (k0 + 32));
#pragma unroll
                for (int i = 0; i < 4; i++)
                    bv[l][i] = Bldg[(size_t)(k0 + 32 + 4 * (qb + l) + i) * N];
            }
        }

        const uint32_t abase = smem_s + buf * BUF_STRIDE;
        const uint32_t bbase = abase + MAT_BUF_BYTES;
#pragma unroll
        for (int ks = 0; ks < 4; ks++) {
            const uint32_t ao = abase + ks * KSBLK_BYTES;
            const uint32_t bo = bbase + ks * KSBLK_BYTES;
            uint4 afv[4];
            uint2 bfv[4];
#pragma unroll
            for (int mt = 0; mt < 4; mt++) ldsm_x4(afv[mt], ao + a_ld[mt]);
#pragma unroll
            for (int nt = 0; nt < 4; nt++) ldsm_x2(bfv[nt], bo + b_ld[nt]);
#pragma unroll
            for (int mt = 0; mt < 4; mt++) {
                const uint32_t af[4] = {afv[mt].x, afv[mt].y, afv[mt].z, afv[mt].w};
#pragma unroll
                for (int nt = 0; nt < 4; nt++) {
                    const uint32_t bf[2] = {bfv[nt].x, bfv[nt].y};
                    mma_tf32(acc[mt][nt], af, bf);
                }
            }
        }

        if (more) {
            char* ab = smem_c + (buf ^ 1) * BUF_STRIDE;
            char* bb = ab + MAT_BUF_BYTES;
#pragma unroll
            for (int l = 0; l < 4; l++) {
                uint4 ta;
                ta.x = to_tf32(pa[l].x); ta.y = to_tf32(pa[l].y);
                ta.z = to_tf32(pa[l].z); ta.w = to_tf32(pa[l].w);
                *(uint4*)(ab + a_sts[l]) = ta;
                uint4 tb;
                tb.x = to_tf32(bv[l][0]); tb.y = to_tf32(bv[l][1]);
                tb.z = to_tf32(bv[l][2]); tb.w = to_tf32(bv[l][3]);
                *(uint4*)(bb + b_sts[l]) = tb;
            }
            __syncthreads();
            buf ^= 1;
        }
    }

    // Epilogue: c-fragment (mt,nt) covers rows {r0, r0+8}, cols {c0, c0+1}
#pragma unroll
    for (int mt = 0; mt < 4; mt++) {
        const int rbase = m0 + wm0 + mt * 16 + g;
#pragma unroll
        for (int nt = 0; nt < 4; nt++) {
            const int cbase = n0 + wn0 + nt * 8 + tig * 2;
#pragma unroll
            for (int e = 0; e < 4; e++) {
                const int r = rbase + (e >> 1) * 8;
                const int c = cbase + (e & 1);
                const float val = acc[mt][nt][e] + bias[c];
                const int b = r >> 10;
                const int s = r & 1023;
                if (MODE == 0) {
                    const int h = c >> 7;
                    const int w = c & 127;
                    if (w < 64)
                        g_Q[(((size_t)(b * NH + h)) * NS + s) * HD + w] = val;
                    else
                        g_K[(((size_t)(b * NH + h)) * NS + s) * HD + (w - 64)] = val;
                } else if (MODE == 1) {
                    const int h = c >> 6;
                    const int d = c & 63;
                    g_V[(((size_t)(b * NH + h)) * NS + s) * HD + d] = val;
                } else {
                    out[(size_t)r * N + c] = val;
                }
            }
        }
    }
}

// ---------------------------------------------------------------------------
// Flash attention on tensor cores (tf32 mma.m16n8k8). R7 version, unchanged.
// ---------------------------------------------------------------------------
#define QS_STR 68
#define KS_STR 68
#define VS_STR 72
#define PS_STR 68
#define QS_OFF 0
#define KS_OFF (64 * QS_STR)
#define VS_OFF (KS_OFF + 64 * KS_STR)
#define PS_OFF (VS_OFF + 64 * VS_STR)
#define ATTN_SMEM_U32 (PS_OFF + 64 * PS_STR)
#define ATTN_SMEM_BYTES (ATTN_SMEM_U32 * 4)

__global__ __launch_bounds__(128) void attn_kernel()
{
    extern __shared__ uint32_t sh[];
    uint32_t* Qs = sh + QS_OFF;
    uint32_t* Ks = sh + KS_OFF;
    uint32_t* Vs = sh + VS_OFF;
    uint32_t* Ps = sh + PS_OFF;

    const int tid  = threadIdx.x;
    const int lane = tid & 31;
    const int warp = tid >> 5;
    const int g    = lane >> 2;
    const int tig  = lane & 3;
    const int wrow = warp * 16;

    const int qt = blockIdx.x;
    const int bh = blockIdx.y;

    const float* Qg  = g_Q + ((size_t)bh * NS + qt * 64) * HD;
    const float* Kg0 = g_K + (size_t)bh * NS * HD;
    const float* Vg0 = g_V + (size_t)bh * NS * HD;

    for (int f = tid; f < 1024; f += 128) {
        const int row = f >> 4;
        const int d4  = (f & 15) << 2;
        float4 v = *(const float4*)(Qg + row * HD + d4);
        uint4 t;
        t.x = to_tf32(v.x * 0.125f); t.y = to_tf32(v.y * 0.125f);
        t.z = to_tf32(v.z * 0.125f); t.w = to_tf32(v.w * 0.125f);
        *(uint4*)(&Qs[row * QS_STR + d4]) = t;
    }

    float oacc[8][4];
#pragma unroll
    for (int nt = 0; nt < 8; nt++)
#pragma unroll
        for (int e = 0; e < 4; e++) oacc[nt][e] = 0.0f;
    float M0 = -1e30f, M1 = -1e30f, L0 = 0.0f, L1 = 0.0f;

    for (int kt = 0; kt < 16; kt++) {
        const float* Kg = Kg0 + (size_t)kt * 64 * HD;
        const float* Vg = Vg0 + (size_t)kt * 64 * HD;
        __syncthreads();
        for (int f = tid; f < 1024; f += 128) {
            const int row = f >> 4;
            const int d4  = (f & 15) << 2;
            float4 kv = *(const float4*)(Kg + row * HD + d4);
            float4 vv = *(const float4*)(Vg + row * HD + d4);
            uint4 tk, tv;
            tk.x = to_tf32(kv.x); tk.y = to_tf32(kv.y);
            tk.z = to_tf32(kv.z); tk.w = to_tf32(kv.w);
            tv.x = to_tf32(vv.x); tv.y = to_tf32(vv.y);
            tv.z = to_tf32(vv.z); tv.w = to_tf32(vv.w);
            *(uint4*)(&Ks[row * KS_STR + d4]) = tk;
            *(uint4*)(&Vs[row * VS_STR + d4]) = tv;
        }
        __syncthreads();

        float sacc[8][4];
#pragma unroll
        for (int nt = 0; nt < 8; nt++)
#pragma unroll
            for (int e = 0; e < 4; e++) sacc[nt][e] = 0.0f;

#pragma unroll
        for (int ks = 0; ks < 8; ks++) {
            const int k8 = ks * 8;
            uint32_t af[4];
            af[0] = Qs[(wrow + g)     * QS_STR + k8 + tig];
            af[1] = Qs[(wrow + g + 8) * QS_STR + k8 + tig];
            af[2] = Qs[(wrow + g)     * QS_STR + k8 + tig + 4];
            af[3] = Qs[(wrow + g + 8) * QS_STR + k8 + tig + 4];
#pragma unroll
            for (int nt = 0; nt < 8; nt++) {
                uint32_t bf[2];
                bf[0] = Ks[(nt * 8 + g) * KS_STR + k8 + tig];
                bf[1] = Ks[(nt * 8 + g) * KS_STR + k8 + tig + 4];
                mma_tf32(sacc[nt], af, bf);
            }
        }

        float rm0 = -1e30f, rm1 = -1e30f;
#pragma unroll
        for (int nt = 0; nt < 8; nt++) {
            rm0 = fmaxf(rm0, fmaxf(sacc[nt][0], sacc[nt][1]));
            rm1 = fmaxf(rm1, fmaxf(sacc[nt][2], sacc[nt][3]));
        }
        rm0 = fmaxf(rm0, __shfl_xor_sync(0xffffffffu, rm0, 1));
        rm0 = fmaxf(rm0, __shfl_xor_sync(0xffffffffu, rm0, 2));
        rm1 = fmaxf(rm1, __shfl_xor_sync(0xffffffffu, rm1, 1));
        rm1 = fmaxf(rm1, __shfl_xor_sync(0xffffffffu, rm1, 2));

        const float mn0 = fmaxf(M0, rm0);
        const float mn1 = fmaxf(M1, rm1);
        const float fac0 = __expf(M0 - mn0);
        const float fac1 = __expf(M1 - mn1);
        float rs0 = 0.0f, rs1 = 0.0f;
#pragma unroll
        for (int nt = 0; nt < 8; nt++) {
            float p0 = __expf(sacc[nt][0] - mn0);
            float p1 = __expf(sacc[nt][1] - mn0);
            float p2 = __expf(sacc[nt][2] - mn1);
            float p3 = __expf(sacc[nt][3] - mn1);
            rs0 += p0 + p1;
            rs1 += p2 + p3;
            uint2 u0, u1;
            u0.x = to_tf32(p0); u0.y = to_tf32(p1);
            u1.x = to_tf32(p2); u1.y = to_tf32(p3);
            *(uint2*)(&Ps[(wrow + g)     * PS_STR + nt * 8 + 2 * tig]) = u0;
            *(uint2*)(&Ps[(wrow + g + 8) * PS_STR + nt * 8 + 2 * tig]) = u1;
        }
        rs0 += __shfl_xor_sync(0xffffffffu, rs0, 1);
        rs0 += __shfl_xor_sync(0xffffffffu, rs0, 2);
        rs1 += __shfl_xor_sync(0xffffffffu, rs1, 1);
        rs1 += __shfl_xor_sync(0xffffffffu, rs1, 2);
        L0 = L0 * fac0 + rs0;
        L1 = L1 * fac1 + rs1;
        M0 = mn0; M1 = mn1;
#pragma unroll
        for (int nt = 0; nt < 8; nt++) {
            oacc[nt][0] *= fac0; oacc[nt][1] *= fac0;
            oacc[nt][2] *= fac1; oacc[nt][3] *= fac1;
        }
        __syncwarp();

#pragma unroll
        for (int ks = 0; ks < 8; ks++) {
            const int k8 = ks * 8;
            uint32_t af[4];
            af[0] = Ps[(wrow + g)     * PS_STR + k8 + tig];
            af[1] = Ps[(wrow + g + 8) * PS_STR + k8 + tig];
            af[2] = Ps[(wrow + g)     * PS_STR + k8 + tig + 4];
            af[3] = Ps[(wrow + g + 8) * PS_STR + k8 + tig + 4];
#pragma unroll
            for (int nt = 0; nt < 8; nt++) {
                uint32_t bf[2];
                bf[0] = Vs[(k8 + tig)     * VS_STR + nt * 8 + g];
                bf[1] = Vs[(k8 + tig + 4) * VS_STR + nt * 8 + g];
                mma_tf32(oacc[nt], af, bf);
            }
        }
        __syncwarp();
    }

    const int b = bh >> 4;
    const int h = bh & 15;
    const float inv0 = 1.0f / L0;
    const float inv1 = 1.0f / L1;
    const int sr0 = qt * 64 + wrow + g;
    float* out0 = g_ctx + ((size_t)(b * NS + sr0))     * ND + h * HD;
    float* out1 = g_ctx + ((size_t)(b * NS + sr0 + 8)) * ND + h * HD;
#pragma unroll
    for (int nt = 0; nt < 8; nt++) {
        const int c = nt * 8 + 2 * tig;
        *(float2*)(out0 + c) = make_float2(oacc[nt][0] * inv0, oacc[nt][1] * inv0);
        *(float2*)(out1 + c) = make_float2(oacc[nt][2] * inv1, oacc[nt][3] * inv1);
    }
}

// ---------------------------------------------------------------------------
extern "C" void kernel_launch(void* const* d_in, const int* in_sizes, int n_in,
                              void* d_out, int out_size)
{
    const float* in_q = (const float*)d_in[0];
    const float* enc  = (const float*)d_in[1];
    const float* Wqk  = (const float*)d_in[2];
    const float* bqk  = (const float*)d_in[3];
    const float* Wv   = (const float*)d_in[4];
    const float* bv   = (const float*)d_in[5];
    const float* Wo   = (const float*)d_in[6];
    const float* bo   = (const float*)d_in[7];
    float* out = (float*)d_out;

    cudaFuncSetAttribute(gemm_tf32<0>,
                         cudaFuncAttributeMaxDynamicSharedMemorySize,
                         GEMM_SMEM_BYTES);
    cudaFuncSetAttribute(gemm_tf32<1>,
                         cudaFuncAttributeMaxDynamicSharedMemorySize,
                         GEMM_SMEM_BYTES);
    cudaFuncSetAttribute(gemm_tf32<2>,
                         cudaFuncAttributeMaxDynamicSharedMemorySize,
                         GEMM_SMEM_BYTES);
    cudaFuncSetAttribute(attn_kernel,
                         cudaFuncAttributeMaxDynamicSharedMemorySize,
                         ATTN_SMEM_BYTES);

    gemm_tf32<0><<<dim3(2048 / 128, 8192 / 128), 256, GEMM_SMEM_BYTES>>>(enc, Wqk, bqk, nullptr, 1024, 2048);
    gemm_tf32<1><<<dim3(1024 / 128, 8192 / 128), 256, GEMM_SMEM_BYTES>>>(in_q, Wv, bv, nullptr, 1024, 1024);
    attn_kernel<<<dim3(16, 128), 128, ATTN_SMEM_BYTES>>>();
    gemm_tf32<2><<<dim3(1024 / 128, 8192 / 128), 256, GEMM_SMEM_BYTES>>>(nullptr, Wo, bo, out, 1024, 1024);
}

// round 11
// speedup vs baseline: 2.3268x; 1.0134x over previous
#include <cuda_runtime.h>
#include <math.h>
#include <stdint.h>

// Problem constants: B=8, S=1024, D=1024, H=16, hd=64
#define NB 8
#define NS 1024
#define ND 1024
#define NH 16
#define HD 64

// Scratch (allocation-free rule: __device__ globals)
__device__ float g_Q[NB * NH * NS * HD];   // [B,H,S,hd]
__device__ float g_K[NB * NH * NS * HD];
__device__ float g_V[NB * NH * NS * HD];
__device__ float g_ctx[NB * NS * ND];      // [B,S,D]

// tf32 lives in a b32 container: cvt dst must be a .b32 register.
__device__ __forceinline__ uint32_t to_tf32(float x) {
    uint32_t r;
    asm("cvt.rna.tf32.f32 %0, %1;" : "=r"(r) : "f"(x));
    return r;
}

__device__ __forceinline__ void mma_tf32(float c[4], const uint32_t a[4], const uint32_t b[2]) {
    asm volatile(
        "mma.sync.aligned.m16n8k8.row.col.f32.tf32.tf32.f32 "
        "{%0,%1,%2,%3}, {%4,%5,%6,%7}, {%8,%9}, {%0,%1,%2,%3};"
        : "+f"(c[0]), "+f"(c[1]), "+f"(c[2]), "+f"(c[3])
        : "r"(a[0]), "r"(a[1]), "r"(a[2]), "r"(a[3]), "r"(b[0]), "r"(b[1]));
}

__device__ __forceinline__ void ldsm_x4(uint4& d, uint32_t saddr) {
    asm volatile("ldmatrix.sync.aligned.m8n8.x4.shared.b16 {%0,%1,%2,%3}, [%4];"
        : "=r"(d.x), "=r"(d.y), "=r"(d.z), "=r"(d.w) : "r"(saddr));
}
__device__ __forceinline__ void ldsm_x2(uint2& d, uint32_t saddr) {
    asm volatile("ldmatrix.sync.aligned.m8n8.x2.shared.b16 {%0,%1}, [%2];"
        : "=r"(d.x), "=r"(d.y) : "r"(saddr));
}

// ---------------------------------------------------------------------------
// tf32 GEMM with ldmatrix + conflict-free padded layout, double-buffered.
// (R9 passing version, unchanged.)
// ---------------------------------------------------------------------------
#define KSBLK_BYTES 6176                     // 386 units * 16B
#define MAT_BUF_BYTES (4 * KSBLK_BYTES)      // 24704 per matrix per buffer
#define BUF_STRIDE (2 * MAT_BUF_BYTES)       // 49408 (A then B)
#define GEMM_SMEM_BYTES (2 * BUF_STRIDE)     // 98816

template <int MODE>
__global__ __launch_bounds__(256) void gemm_tf32(
    const float* __restrict__ A, const float* __restrict__ Bw,
    const float* __restrict__ bias, float* __restrict__ out,
    int K, int N)
{
    extern __shared__ uint32_t dynsh[];
    char* smem_c = (char*)dynsh;
    const uint32_t smem_s = (uint32_t)__cvta_generic_to_shared(dynsh);

    const int tid  = threadIdx.x;
    const int lane = tid & 31;
    const int warp = tid >> 5;
    const int g    = lane >> 2;
    const int tig  = lane & 3;
    const int wm0 = (warp >> 2) * 64;
    const int wn0 = (warp & 3) * 32;

    const int m0 = blockIdx.y * 128;
    const int n0 = blockIdx.x * 128;

    const float* Ap = (MODE == 2) ? (const float*)g_ctx : A;

    const int ra = tid >> 3;
    const int kc = (tid & 7) * 4;
    const float* Aldg = Ap + (size_t)(m0 + ra) * K + kc;

    const int nB = tid & 127;
    const int qb = (tid >> 7) * 4;
    const float* Bldg = Bw + n0 + nB;

    const int ksA = kc >> 3, hA = (kc >> 2) & 1;
    uint32_t a_sts[4], b_sts[4];
#pragma unroll
    for (int l = 0; l < 4; l++) {
        const int m = ra + 32 * l;
        a_sts[l] = (uint32_t)(ksA * KSBLK_BYTES + m * 48 + hA * 16);
        const int q = qb + l;
        b_sts[l] = (uint32_t)((q >> 1) * KSBLK_BYTES + nB * 48 + (q & 1) * 16);
    }

    uint32_t a_ld[4], b_ld[4];
    {
        const int rl   = ((lane >> 3) & 1) * 8 + (lane & 7);
        const int hsel = lane >> 4;
#pragma unroll
        for (int mt = 0; mt < 4; mt++)
            a_ld[mt] = (uint32_t)((wm0 + mt * 16 + rl) * 48 + hsel * 16);
        const int nl    = lane & 7;
        const int hsel2 = (lane >> 3) & 1;
#pragma unroll
        for (int nt = 0; nt < 4; nt++)
            b_ld[nt] = (uint32_t)((wn0 + nt * 8 + nl) * 48 + hsel2 * 16);
    }

    float acc[4][4][4];
#pragma unroll
    for (int mt = 0; mt < 4; mt++)
#pragma unroll
        for (int nt = 0; nt < 4; nt++)
#pragma unroll
            for (int e = 0; e < 4; e++) acc[mt][nt][e] = 0.0f;

    float4 pa[4];
    float  bv[4][4];

#pragma unroll
    for (int l = 0; l < 4; l++) {
        pa[l] = *(const float4*)(Aldg + (size_t)(l * 32) * K);
#pragma unroll
        for (int i = 0; i < 4; i++)
            bv[l][i] = Bldg[(size_t)(4 * (qb + l) + i) * N];
    }
    {
        char* ab = smem_c;
        char* bb = smem_c + MAT_BUF_BYTES;
#pragma unroll
        for (int l = 0; l < 4; l++) {
            uint4 ta;
            ta.x = to_tf32(pa[l].x); ta.y = to_tf32(pa[l].y);
            ta.z = to_tf32(pa[l].z); ta.w = to_tf32(pa[l].w);
            *(uint4*)(ab + a_sts[l]) = ta;
            uint4 tb;
            tb.x = to_tf32(bv[l][0]); tb.y = to_tf32(bv[l][1]);
            tb.z = to_tf32(bv[l][2]); tb.w = to_tf32(bv[l][3]);
            *(uint4*)(bb + b_sts[l]) = tb;
        }
    }
    __syncthreads();

    int buf = 0;
    for (int k0 = 0; k0 < K; k0 += 32) {
        const bool more = (k0 + 32 < K);
        if (more) {
#pragma unroll
            for (int l = 0; l < 4; l++) {
                pa[l] = *(const float4*)(Aldg + (size_t)(l * 32) * K + (k0 + 32));
#pragma unroll
                for (int i = 0; i < 4; i++)
                    bv[l][i] = Bldg[(size_t)(k0 + 32 + 4 * (qb + l) + i) * N];
            }
        }

        const uint32_t abase = smem_s + buf * BUF_STRIDE;
        const uint32_t bbase = abase + MAT_BUF_BYTES;
#pragma unroll
        for (int ks = 0; ks < 4; ks++) {
            const uint32_t ao = abase + ks * KSBLK_BYTES;
            const uint32_t bo = bbase + ks * KSBLK_BYTES;
            uint4 afv[4];
            uint2 bfv[4];
#pragma unroll
            for (int mt = 0; mt < 4; mt++) ldsm_x4(afv[mt], ao + a_ld[mt]);
#pragma unroll
            for (int nt = 0; nt < 4; nt++) ldsm_x2(bfv[nt], bo + b_ld[nt]);
#pragma unroll
            for (int mt = 0; mt < 4; mt++) {
                const uint32_t af[4] = {afv[mt].x, afv[mt].y, afv[mt].z, afv[mt].w};
#pragma unroll
                for (int nt = 0; nt < 4; nt++) {
                    const uint32_t bf[2] = {bfv[nt].x, bfv[nt].y};
                    mma_tf32(acc[mt][nt], af, bf);
                }
            }
        }

        if (more) {
            char* ab = smem_c + (buf ^ 1) * BUF_STRIDE;
            char* bb = ab + MAT_BUF_BYTES;
#pragma unroll
            for (int l = 0; l < 4; l++) {
                uint4 ta;
                ta.x = to_tf32(pa[l].x); ta.y = to_tf32(pa[l].y);
                ta.z = to_tf32(pa[l].z); ta.w = to_tf32(pa[l].w);
                *(uint4*)(ab + a_sts[l]) = ta;
                uint4 tb;
                tb.x = to_tf32(bv[l][0]); tb.y = to_tf32(bv[l][1]);
                tb.z = to_tf32(bv[l][2]); tb.w = to_tf32(bv[l][3]);
                *(uint4*)(bb + b_sts[l]) = tb;
            }
            __syncthreads();
            buf ^= 1;
        }
    }

#pragma unroll
    for (int mt = 0; mt < 4; mt++) {
        const int rbase = m0 + wm0 + mt * 16 + g;
#pragma unroll
        for (int nt = 0; nt < 4; nt++) {
            const int cbase = n0 + wn0 + nt * 8 + tig * 2;
#pragma unroll
            for (int e = 0; e < 4; e++) {
                const int r = rbase + (e >> 1) * 8;
                const int c = cbase + (e & 1);
                const float val = acc[mt][nt][e] + bias[c];
                const int b = r >> 10;
                const int s = r & 1023;
                if (MODE == 0) {
                    const int h = c >> 7;
                    const int w = c & 127;
                    if (w < 64)
                        g_Q[(((size_t)(b * NH + h)) * NS + s) * HD + w] = val;
                    else
                        g_K[(((size_t)(b * NH + h)) * NS + s) * HD + (w - 64)] = val;
                } else if (MODE == 1) {
                    const int h = c >> 6;
                    const int d = c & 63;
                    g_V[(((size_t)(b * NH + h)) * NS + s) * HD + d] = val;
                } else {
                    out[(size_t)r * N + c] = val;
                }
            }
        }
    }
}

// ---------------------------------------------------------------------------
// Flash attention, fully ldmatrix-based (same padded tile layout as GEMM).
// 64x64 tf32 tile: byte(ks, row, h) = ks*3104 + row*48 + h*16, ks = k>>3.
//   Q: A-tile (rows = q-row, k = d)  -> staged once, fragments hoisted to regs
//   K: B-tile (rows = j,    k = d)  -> natural [j][d] store, conflict-free
//   P: A-tile (rows = q-row, k = j) -> softmax writes land in fragment layout
//   V: B-tile (rows = d,    k = j)  -> transposed at load (coalesced LDG.32)
// P shares the Q staging region. ldsm_x4 on B covers 2 k-steps per load.
// ---------------------------------------------------------------------------
#define ATILE_KSB 3104
#define ATILE_BYTES (8 * ATILE_KSB)          // 24832
#define PQ_OFF 0
#define KT_OFF ATILE_BYTES
#define VT_OFF (2 * ATILE_BYTES)
#define ATTN_SMEM_BYTES (3 * ATILE_BYTES)    // 74496

__global__ __launch_bounds__(128, 3) void attn_kernel()
{
    extern __shared__ uint32_t sh[];
    char* smc = (char*)sh;
    const uint32_t smem_s = (uint32_t)__cvta_generic_to_shared(sh);

    const int tid  = threadIdx.x;
    const int lane = tid & 31;
    const int warp = tid >> 5;
    const int g    = lane >> 2;
    const int tig  = lane & 3;
    const int wrow = warp * 16;

    const int qt = blockIdx.x;
    const int bh = blockIdx.y;

    const float* Qg  = g_Q + ((size_t)bh * NS + qt * 64) * HD;
    const float* Kg0 = g_K + (size_t)bh * NS * HD;
    const float* Vg0 = g_V + (size_t)bh * NS * HD;

    // Per-lane ldsm offsets
    const uint32_t a_ld_lane = (uint32_t)((lane & 15) * 48 + (lane >> 4) * 16);
    const uint32_t b_ld4 = (uint32_t)(((lane >> 4) & 1) * ATILE_KSB
                                      + ((lane >> 3) & 1) * 16 + (lane & 7) * 48);

    // ---- Stage Q (scale folded), hoist fragments to registers ----
    for (int f = tid; f < 1024; f += 128) {
        const int row = f >> 4;
        const int d4  = (f & 15) << 2;
        float4 v = *(const float4*)(Qg + row * HD + d4);
        uint4 t;
        t.x = to_tf32(v.x * 0.125f); t.y = to_tf32(v.y * 0.125f);
        t.z = to_tf32(v.z * 0.125f); t.w = to_tf32(v.w * 0.125f);
        *(uint4*)(smc + PQ_OFF + (d4 >> 3) * ATILE_KSB + row * 48 + ((d4 >> 2) & 1) * 16) = t;
    }
    __syncthreads();
    uint4 qf[8];
#pragma unroll
    for (int ks = 0; ks < 8; ks++)
        ldsm_x4(qf[ks], smem_s + PQ_OFF + ks * ATILE_KSB + wrow * 48 + a_ld_lane);

    float oacc[8][4];
#pragma unroll
    for (int nt = 0; nt < 8; nt++)
#pragma unroll
        for (int e = 0; e < 4; e++) oacc[nt][e] = 0.0f;
    float M0 = -1e30f, M1 = -1e30f, L0 = 0.0f, L1 = 0.0f;

    for (int kt = 0; kt < 16; kt++) {
        const float* Kg = Kg0 + (size_t)kt * 64 * HD;
        const float* Vg = Vg0 + (size_t)kt * 64 * HD;
        __syncthreads();   // previous readers done (also fences Q ldsm at kt=0)

        // K tile: natural rows, conflict-free STS.128
        for (int f = tid; f < 1024; f += 128) {
            const int row = f >> 4;
            const int d4  = (f & 15) << 2;
            float4 kv = *(const float4*)(Kg + row * HD + d4);
            uint4 t;
            t.x = to_tf32(kv.x); t.y = to_tf32(kv.y);
            t.z = to_tf32(kv.z); t.w = to_tf32(kv.w);
            *(uint4*)(smc + KT_OFF + (d4 >> 3) * ATILE_KSB + row * 48 + ((d4 >> 2) & 1) * 16) = t;
        }
        // V tile transposed: thread owns (d, j0..j0+3); coalesced LDG.32
        for (int i = 0; i < 8; i++) {
            const int f  = i * 128 + tid;
            const int d  = f & 63;
            const int j0 = (f >> 6) * 4;
            uint4 t;
            t.x = to_tf32(Vg[(j0 + 0) * HD + d]);
            t.y = to_tf32(Vg[(j0 + 1) * HD + d]);
            t.z = to_tf32(Vg[(j0 + 2) * HD + d]);
            t.w = to_tf32(Vg[(j0 + 3) * HD + d]);
            *(uint4*)(smc + VT_OFF + (j0 >> 3) * ATILE_KSB + d * 48 + ((j0 >> 2) & 1) * 16) = t;
        }
        __syncthreads();

        // ---- S = Q @ K^T ----
        float sacc[8][4];
#pragma unroll
        for (int nt = 0; nt < 8; nt++)
#pragma unroll
            for (int e = 0; e < 4; e++) sacc[nt][e] = 0.0f;

#pragma unroll
        for (int ks2 = 0; ks2 < 4; ks2++) {
            const uint32_t kbase = smem_s + KT_OFF + ks2 * 2 * ATILE_KSB;
            uint4 bk[8];
#pragma unroll
            for (int nt = 0; nt < 8; nt++)
                ldsm_x4(bk[nt], kbase + nt * 8 * 48 + b_ld4);
            const uint32_t af0[4] = {qf[2 * ks2].x, qf[2 * ks2].y, qf[2 * ks2].z, qf[2 * ks2].w};
            const uint32_t af1[4] = {qf[2 * ks2 + 1].x, qf[2 * ks2 + 1].y, qf[2 * ks2 + 1].z, qf[2 * ks2 + 1].w};
#pragma unroll
            for (int nt = 0; nt < 8; nt++) {
                const uint32_t bf0[2] = {bk[nt].x, bk[nt].y};
                const uint32_t bf1[2] = {bk[nt].z, bk[nt].w};
                mma_tf32(sacc[nt], af0, bf0);
                mma_tf32(sacc[nt], af1, bf1);
            }
        }

        // ---- online softmax (rows g, g+8) ----
        float rm0 = -1e30f, rm1 = -1e30f;
#pragma unroll
        for (int nt = 0; nt < 8; nt++) {
            rm0 = fmaxf(rm0, fmaxf(sacc[nt][0], sacc[nt][1]));
            rm1 = fmaxf(rm1, fmaxf(sacc[nt][2], sacc[nt][3]));
        }
        rm0 = fmaxf(rm0, __shfl_xor_sync(0xffffffffu, rm0, 1));
        rm0 = fmaxf(rm0, __shfl_xor_sync(0xffffffffu, rm0, 2));
        rm1 = fmaxf(rm1, __shfl_xor_sync(0xffffffffu, rm1, 1));
        rm1 = fmaxf(rm1, __shfl_xor_sync(0xffffffffu, rm1, 2));

        const float mn0 = fmaxf(M0, rm0);
        const float mn1 = fmaxf(M1, rm1);
        const float fac0 = __expf(M0 - mn0);
        const float fac1 = __expf(M1 - mn1);
        float rs0 = 0.0f, rs1 = 0.0f;
#pragma unroll
        for (int nt = 0; nt < 8; nt++) {
            float p0 = __expf(sacc[nt][0] - mn0);
            float p1 = __expf(sacc[nt][1] - mn0);
            float p2 = __expf(sacc[nt][2] - mn1);
            float p3 = __expf(sacc[nt][3] - mn1);
            rs0 += p0 + p1;
            rs1 += p2 + p3;
            uint2 u0, u1;
            u0.x = to_tf32(p0); u0.y = to_tf32(p1);
            u1.x = to_tf32(p2); u1.y = to_tf32(p3);
            // P tile: A-layout, k = j: byte = nt*3104 + row*48 + tig*8
            *(uint2*)(smc + PQ_OFF + nt * ATILE_KSB + (wrow + g) * 48 + tig * 8) = u0;
            *(uint2*)(smc + PQ_OFF + nt * ATILE_KSB + (wrow + g + 8) * 48 + tig * 8) = u1;
        }
        rs0 += __shfl_xor_sync(0xffffffffu, rs0, 1);
        rs0 += __shfl_xor_sync(0xffffffffu, rs0, 2);
        rs1 += __shfl_xor_sync(0xffffffffu, rs1, 1);
        rs1 += __shfl_xor_sync(0xffffffffu, rs1, 2);
        L0 = L0 * fac0 + rs0;
        L1 = L1 * fac1 + rs1;
        M0 = mn0; M1 = mn1;
#pragma unroll
        for (int nt = 0; nt < 8; nt++) {
            oacc[nt][0] *= fac0; oacc[nt][1] *= fac0;
            oacc[nt][2] *= fac1; oacc[nt][3] *= fac1;
        }
        __syncwarp();     // P rows are per-warp

        // ---- O += P @ V ----
#pragma unroll
        for (int ks2 = 0; ks2 < 4; ks2++) {
            uint4 pf0, pf1;
            ldsm_x4(pf0, smem_s + PQ_OFF + (2 * ks2)     * ATILE_KSB + wrow * 48 + a_ld_lane);
            ldsm_x4(pf1, smem_s + PQ_OFF + (2 * ks2 + 1) * ATILE_KSB + wrow * 48 + a_ld_lane);
            const uint32_t pa0[4] = {pf0.x, pf0.y, pf0.z, pf0.w};
            const uint32_t pa1[4] = {pf1.x, pf1.y, pf1.z, pf1.w};
            const uint32_t vbase = smem_s + VT_OFF + ks2 * 2 * ATILE_KSB;
            uint4 bvv[8];
#pragma unroll
            for (int nt = 0; nt < 8; nt++)
                ldsm_x4(bvv[nt], vbase + nt * 8 * 48 + b_ld4);
#pragma unroll
            for (int nt = 0; nt < 8; nt++) {
                const uint32_t bf0[2] = {bvv[nt].x, bvv[nt].y};
                const uint32_t bf1[2] = {bvv[nt].z, bvv[nt].w};
                mma_tf32(oacc[nt], pa0, bf0);
                mma_tf32(oacc[nt], pa1, bf1);
            }
        }
        __syncwarp();     // done reading P before next overwrite
    }

    // Finalize: divide by L, write ctx [B,S,D]  (D col = h*64 + d)
    const int b = bh >> 4;
    const int h = bh & 15;
    const float inv0 = 1.0f / L0;
    const float inv1 = 1.0f / L1;
    const int sr0 = qt * 64 + wrow + g;
    float* out0 = g_ctx + ((size_t)(b * NS + sr0))     * ND + h * HD;
    float* out1 = g_ctx + ((size_t)(b * NS + sr0 + 8)) * ND + h * HD;
#pragma unroll
    for (int nt = 0; nt < 8; nt++) {
        const int c = nt * 8 + 2 * tig;
        *(float2*)(out0 + c) = make_float2(oacc[nt][0] * inv0, oacc[nt][1] * inv0);
        *(float2*)(out1 + c) = make_float2(oacc[nt][2] * inv1, oacc[nt][3] * inv1);
    }
}

// ---------------------------------------------------------------------------
extern "C" void kernel_launch(void* const* d_in, const int* in_sizes, int n_in,
                              void* d_out, int out_size)
{
    const float* in_q = (const float*)d_in[0];
    const float* enc  = (const float*)d_in[1];
    const float* Wqk  = (const float*)d_in[2];
    const float* bqk  = (const float*)d_in[3];
    const float* Wv   = (const float*)d_in[4];
    const float* bv   = (const float*)d_in[5];
    const float* Wo   = (const float*)d_in[6];
    const float* bo   = (const float*)d_in[7];
    float* out = (float*)d_out;

    cudaFuncSetAttribute(gemm_tf32<0>,
                         cudaFuncAttributeMaxDynamicSharedMemorySize,
                         GEMM_SMEM_BYTES);
    cudaFuncSetAttribute(gemm_tf32<1>,
                         cudaFuncAttributeMaxDynamicSharedMemorySize,
                         GEMM_SMEM_BYTES);
    cudaFuncSetAttribute(gemm_tf32<2>,
                         cudaFuncAttributeMaxDynamicSharedMemorySize,
                         GEMM_SMEM_BYTES);
    cudaFuncSetAttribute(attn_kernel,
                         cudaFuncAttributeMaxDynamicSharedMemorySize,
                         ATTN_SMEM_BYTES);

    gemm_tf32<0><<<dim3(2048 / 128, 8192 / 128), 256, GEMM_SMEM_BYTES>>>(enc, Wqk, bqk, nullptr, 1024, 2048);
    gemm_tf32<1><<<dim3(1024 / 128, 8192 / 128), 256, GEMM_SMEM_BYTES>>>(in_q, Wv, bv, nullptr, 1024, 1024);
    attn_kernel<<<dim3(16, 128), 128, ATTN_SMEM_BYTES>>>();
    gemm_tf32<2><<<dim3(1024 / 128, 8192 / 128), 256, GEMM_SMEM_BYTES>>>(nullptr, Wo, bo, out, 1024, 1024);
}

// round 12
// speedup vs baseline: 2.4637x; 1.0588x over previous
#include <cuda_runtime.h>
#include <math.h>
#include <stdint.h>

// Problem constants: B=8, S=1024, D=1024, H=16, hd=64
#define NB 8
#define NS 1024
#define ND 1024
#define NH 16
#define HD 64

// Scratch (allocation-free rule: __device__ globals)
__device__ float g_Q[NB * NH * NS * HD];   // [B,H,S,hd]
__device__ float g_K[NB * NH * NS * HD];
__device__ float g_V[NB * NH * NS * HD];
__device__ float g_ctx[NB * NS * ND];      // [B,S,D]

// tf32 lives in a b32 container: cvt dst must be a .b32 register.
__device__ __forceinline__ uint32_t to_tf32(float x) {
    uint32_t r;
    asm("cvt.rna.tf32.f32 %0, %1;" : "=r"(r) : "f"(x));
    return r;
}

__device__ __forceinline__ float ex2f(float x) {
    float r;
    asm("ex2.approx.f32 %0, %1;" : "=f"(r) : "f"(x));
    return r;
}

__device__ __forceinline__ void mma_tf32(float c[4], const uint32_t a[4], const uint32_t b[2]) {
    asm volatile(
        "mma.sync.aligned.m16n8k8.row.col.f32.tf32.tf32.f32 "
        "{%0,%1,%2,%3}, {%4,%5,%6,%7}, {%8,%9}, {%0,%1,%2,%3};"
        : "+f"(c[0]), "+f"(c[1]), "+f"(c[2]), "+f"(c[3])
        : "r"(a[0]), "r"(a[1]), "r"(a[2]), "r"(a[3]), "r"(b[0]), "r"(b[1]));
}

__device__ __forceinline__ void ldsm_x4(uint4& d, uint32_t saddr) {
    asm volatile("ldmatrix.sync.aligned.m8n8.x4.shared.b16 {%0,%1,%2,%3}, [%4];"
        : "=r"(d.x), "=r"(d.y), "=r"(d.z), "=r"(d.w) : "r"(saddr));
}
__device__ __forceinline__ void ldsm_x2(uint2& d, uint32_t saddr) {
    asm volatile("ldmatrix.sync.aligned.m8n8.x2.shared.b16 {%0,%1}, [%2];"
        : "=r"(d.x), "=r"(d.y) : "r"(saddr));
}

// ---------------------------------------------------------------------------
// tf32 GEMM with ldmatrix + conflict-free padded layout, double-buffered.
// (R9 passing version, unchanged.)
// ---------------------------------------------------------------------------
#define KSBLK_BYTES 6176                     // 386 units * 16B
#define MAT_BUF_BYTES (4 * KSBLK_BYTES)      // 24704 per matrix per buffer
#define BUF_STRIDE (2 * MAT_BUF_BYTES)       // 49408 (A then B)
#define GEMM_SMEM_BYTES (2 * BUF_STRIDE)     // 98816

template <int MODE>
__global__ __launch_bounds__(256) void gemm_tf32(
    const float* __restrict__ A, const float* __restrict__ Bw,
    const float* __restrict__ bias, float* __restrict__ out,
    int K, int N)
{
    extern __shared__ uint32_t dynsh[];
    char* smem_c = (char*)dynsh;
    const uint32_t smem_s = (uint32_t)__cvta_generic_to_shared(dynsh);

    const int tid  = threadIdx.x;
    const int lane = tid & 31;
    const int warp = tid >> 5;
    const int g    = lane >> 2;
    const int tig  = lane & 3;
    const int wm0 = (warp >> 2) * 64;
    const int wn0 = (warp & 3) * 32;

    const int m0 = blockIdx.y * 128;
    const int n0 = blockIdx.x * 128;

    const float* Ap = (MODE == 2) ? (const float*)g_ctx : A;

    const int ra = tid >> 3;
    const int kc = (tid & 7) * 4;
    const float* Aldg = Ap + (size_t)(m0 + ra) * K + kc;

    const int nB = tid & 127;
    const int qb = (tid >> 7) * 4;
    const float* Bldg = Bw + n0 + nB;

    const int ksA = kc >> 3, hA = (kc >> 2) & 1;
    uint32_t a_sts[4], b_sts[4];
#pragma unroll
    for (int l = 0; l < 4; l++) {
        const int m = ra + 32 * l;
        a_sts[l] = (uint32_t)(ksA * KSBLK_BYTES + m * 48 + hA * 16);
        const int q = qb + l;
        b_sts[l] = (uint32_t)((q >> 1) * KSBLK_BYTES + nB * 48 + (q & 1) * 16);
    }

    uint32_t a_ld[4], b_ld[4];
    {
        const int rl   = ((lane >> 3) & 1) * 8 + (lane & 7);
        const int hsel = lane >> 4;
#pragma unroll
        for (int mt = 0; mt < 4; mt++)
            a_ld[mt] = (uint32_t)((wm0 + mt * 16 + rl) * 48 + hsel * 16);
        const int nl    = lane & 7;
        const int hsel2 = (lane >> 3) & 1;
#pragma unroll
        for (int nt = 0; nt < 4; nt++)
            b_ld[nt] = (uint32_t)((wn0 + nt * 8 + nl) * 48 + hsel2 * 16);
    }

    float acc[4][4][4];
#pragma unroll
    for (int mt = 0; mt < 4; mt++)
#pragma unroll
        for (int nt = 0; nt < 4; nt++)
#pragma unroll
            for (int e = 0; e < 4; e++) acc[mt][nt][e] = 0.0f;

    float4 pa[4];
    float  bv[4][4];

#pragma unroll
    for (int l = 0; l < 4; l++) {
        pa[l] = *(const float4*)(Aldg + (size_t)(l * 32) * K);
#pragma unroll
        for (int i = 0; i < 4; i++)
            bv[l][i] = Bldg[(size_t)(4 * (qb + l) + i) * N];
    }
    {
        char* ab = smem_c;
        char* bb = smem_c + MAT_BUF_BYTES;
#pragma unroll
        for (int l = 0; l < 4; l++) {
            uint4 ta;
            ta.x = to_tf32(pa[l].x); ta.y = to_tf32(pa[l].y);
            ta.z = to_tf32(pa[l].z); ta.w = to_tf32(pa[l].w);
            *(uint4*)(ab + a_sts[l]) = ta;
            uint4 tb;
            tb.x = to_tf32(bv[l][0]); tb.y = to_tf32(bv[l][1]);
            tb.z = to_tf32(bv[l][2]); tb.w = to_tf32(bv[l][3]);
            *(uint4*)(bb + b_sts[l]) = tb;
        }
    }
    __syncthreads();

    int buf = 0;
    for (int k0 = 0; k0 < K; k0 += 32) {
        const bool more = (k0 + 32 < K);
        if (more) {
#pragma unroll
            for (int l = 0; l < 4; l++) {
                pa[l] = *(const float4*)(Aldg + (size_t)(l * 32) * K + (k0 + 32));
#pragma unroll
                for (int i = 0; i < 4; i++)
                    bv[l][i] = Bldg[(size_t)(k0 + 32 + 4 * (qb + l) + i) * N];
            }
        }

        const uint32_t abase = smem_s + buf * BUF_STRIDE;
        const uint32_t bbase = abase + MAT_BUF_BYTES;
#pragma unroll
        for (int ks = 0; ks < 4; ks++) {
            const uint32_t ao = abase + ks * KSBLK_BYTES;
            const uint32_t bo = bbase + ks * KSBLK_BYTES;
            uint4 afv[4];
            uint2 bfv[4];
#pragma unroll
            for (int mt = 0; mt < 4; mt++) ldsm_x4(afv[mt], ao + a_ld[mt]);
#pragma unroll
            for (int nt = 0; nt < 4; nt++) ldsm_x2(bfv[nt], bo + b_ld[nt]);
#pragma unroll
            for (int mt = 0; mt < 4; mt++) {
                const uint32_t af[4] = {afv[mt].x, afv[mt].y, afv[mt].z, afv[mt].w};
#pragma unroll
                for (int nt = 0; nt < 4; nt++) {
                    const uint32_t bf[2] = {bfv[nt].x, bfv[nt].y};
                    mma_tf32(acc[mt][nt], af, bf);
                }
            }
        }

        if (more) {
            char* ab = smem_c + (buf ^ 1) * BUF_STRIDE;
            char* bb = ab + MAT_BUF_BYTES;
#pragma unroll
            for (int l = 0; l < 4; l++) {
                uint4 ta;
                ta.x = to_tf32(pa[l].x); ta.y = to_tf32(pa[l].y);
                ta.z = to_tf32(pa[l].z); ta.w = to_tf32(pa[l].w);
                *(uint4*)(ab + a_sts[l]) = ta;
                uint4 tb;
                tb.x = to_tf32(bv[l][0]); tb.y = to_tf32(bv[l][1]);
                tb.z = to_tf32(bv[l][2]); tb.w = to_tf32(bv[l][3]);
                *(uint4*)(bb + b_sts[l]) = tb;
            }
            __syncthreads();
            buf ^= 1;
        }
    }

#pragma unroll
    for (int mt = 0; mt < 4; mt++) {
        const int rbase = m0 + wm0 + mt * 16 + g;
#pragma unroll
        for (int nt = 0; nt < 4; nt++) {
            const int cbase = n0 + wn0 + nt * 8 + tig * 2;
#pragma unroll
            for (int e = 0; e < 4; e++) {
                const int r = rbase + (e >> 1) * 8;
                const int c = cbase + (e & 1);
                const float val = acc[mt][nt][e] + bias[c];
                const int b = r >> 10;
                const int s = r & 1023;
                if (MODE == 0) {
                    const int h = c >> 7;
                    const int w = c & 127;
                    if (w < 64)
                        g_Q[(((size_t)(b * NH + h)) * NS + s) * HD + w] = val;
                    else
                        g_K[(((size_t)(b * NH + h)) * NS + s) * HD + (w - 64)] = val;
                } else if (MODE == 1) {
                    const int h = c >> 6;
                    const int d = c & 63;
                    g_V[(((size_t)(b * NH + h)) * NS + s) * HD + d] = val;
                } else {
                    out[(size_t)r * N + c] = val;
                }
            }
        }
    }
}

// ---------------------------------------------------------------------------
// Flash attention: 256 threads / 8 warps, 128 Q-rows per CTA, 64-key tiles.
// Each K/V tile load + CTA sync now serves 2x the MMA work vs R11.
// Layouts (all conflict-free, validated pattern):
//   P/Q tile: 128 rows, ks-block stride 6176 (=2 mod 8 units), row stride 48.
//   K tile:   64 rows,  ks-block stride 3104, natural [j][d] store.
//   V tile:   64 rows (d), transposed at load, ks = j-quad blocks.
// Q fragments hoisted to registers; softmax in log2 domain (ex2.approx).
// ---------------------------------------------------------------------------
#define PT_KSB 6176
#define PT_BYTES (8 * PT_KSB)                // 49408
#define ATILE_KSB 3104
#define ATILE_BYTES (8 * ATILE_KSB)          // 24832
#define KT2_OFF PT_BYTES
#define VT2_OFF (PT_BYTES + ATILE_BYTES)
#define ATTN_SMEM_BYTES (PT_BYTES + 2 * ATILE_BYTES)   // 99072

// 0.125 * log2(e): folds softmax scale AND exp->exp2 conversion into Q.
#define QSCALE 0.18033688011112042f

__global__ __launch_bounds__(256, 2) void attn_kernel()
{
    extern __shared__ uint32_t sh[];
    char* smc = (char*)sh;
    const uint32_t smem_s = (uint32_t)__cvta_generic_to_shared(sh);

    const int tid  = threadIdx.x;
    const int lane = tid & 31;
    const int warp = tid >> 5;          // 0..7
    const int g    = lane >> 2;
    const int tig  = lane & 3;
    const int wrow = warp * 16;         // warp's Q-row base (0..112)

    const int qt = blockIdx.x;          // 0..7 (128-row Q blocks)
    const int bh = blockIdx.y;          // 0..127

    const float* Qg  = g_Q + ((size_t)bh * NS + qt * 128) * HD;
    const float* Kg0 = g_K + (size_t)bh * NS * HD;
    const float* Vg0 = g_V + (size_t)bh * NS * HD;

    // Per-lane ldsm offsets (layout-relative)
    const uint32_t a_ld_lane = (uint32_t)((lane & 15) * 48 + (lane >> 4) * 16);
    const uint32_t b_ld4 = (uint32_t)(((lane >> 4) & 1) * ATILE_KSB
                                      + ((lane >> 3) & 1) * 16 + (lane & 7) * 48);

    // ---- Stage Q (scale+log2e folded), hoist fragments to registers ----
#pragma unroll
    for (int i = 0; i < 8; i++) {
        const int f   = i * 256 + tid;       // 0..2047
        const int row = f >> 4;              // 0..127
        const int d4  = (f & 15) << 2;
        float4 v = *(const float4*)(Qg + row * HD + d4);
        uint4 t;
        t.x = to_tf32(v.x * QSCALE); t.y = to_tf32(v.y * QSCALE);
        t.z = to_tf32(v.z * QSCALE); t.w = to_tf32(v.w * QSCALE);
        *(uint4*)(smc + (d4 >> 3) * PT_KSB + row * 48 + ((d4 >> 2) & 1) * 16) = t;
    }
    __syncthreads();
    uint4 qf[8];
#pragma unroll
    for (int ks = 0; ks < 8; ks++)
        ldsm_x4(qf[ks], smem_s + ks * PT_KSB + wrow * 48 + a_ld_lane);

    float oacc[8][4];
#pragma unroll
    for (int nt = 0; nt < 8; nt++)
#pragma unroll
        for (int e = 0; e < 4; e++) oacc[nt][e] = 0.0f;
    float M0 = -1e30f, M1 = -1e30f, L0 = 0.0f, L1 = 0.0f;

    for (int kt = 0; kt < 16; kt++) {
        const float* Kg = Kg0 + (size_t)kt * 64 * HD;
        const float* Vg = Vg0 + (size_t)kt * 64 * HD;
        __syncthreads();   // previous readers done (also fences Q ldsm at kt=0)

        // K tile: natural rows, conflict-free STS.128
#pragma unroll
        for (int i = 0; i < 4; i++) {
            const int f   = i * 256 + tid;   // 0..1023
            const int row = f >> 4;          // 0..63
            const int d4  = (f & 15) << 2;
            float4 kv = *(const float4*)(Kg + row * HD + d4);
            uint4 t;
            t.x = to_tf32(kv.x); t.y = to_tf32(kv.y);
            t.z = to_tf32(kv.z); t.w = to_tf32(kv.w);
            *(uint4*)(smc + KT2_OFF + (d4 >> 3) * ATILE_KSB + row * 48 + ((d4 >> 2) & 1) * 16) = t;
        }
        // V tile transposed: thread owns (d, j0..j0+3); coalesced LDG.32
#pragma unroll
        for (int i = 0; i < 4; i++) {
            const int f  = i * 256 + tid;    // 0..1023
            const int d  = f & 63;
            const int j0 = (f >> 6) * 4;     // 0..60
            uint4 t;
            t.x = to_tf32(Vg[(j0 + 0) * HD + d]);
            t.y = to_tf32(Vg[(j0 + 1) * HD + d]);
            t.z = to_tf32(Vg[(j0 + 2) * HD + d]);
            t.w = to_tf32(Vg[(j0 + 3) * HD + d]);
            *(uint4*)(smc + VT2_OFF + (j0 >> 3) * ATILE_KSB + d * 48 + ((j0 >> 2) & 1) * 16) = t;
        }
        __syncthreads();

        // ---- S = Q @ K^T (log2 domain) ----
        float sacc[8][4];
#pragma unroll
        for (int nt = 0; nt < 8; nt++)
#pragma unroll
            for (int e = 0; e < 4; e++) sacc[nt][e] = 0.0f;

#pragma unroll
        for (int ks2 = 0; ks2 < 4; ks2++) {
            const uint32_t kbase = smem_s + KT2_OFF + ks2 * 2 * ATILE_KSB;
            const uint32_t af0[4] = {qf[2 * ks2].x, qf[2 * ks2].y, qf[2 * ks2].z, qf[2 * ks2].w};
            const uint32_t af1[4] = {qf[2 * ks2 + 1].x, qf[2 * ks2 + 1].y, qf[2 * ks2 + 1].z, qf[2 * ks2 + 1].w};
#pragma unroll
            for (int nt = 0; nt < 8; nt++) {
                uint4 bk;
                ldsm_x4(bk, kbase + nt * 8 * 48 + b_ld4);
                const uint32_t bf0[2] = {bk.x, bk.y};
                const uint32_t bf1[2] = {bk.z, bk.w};
                mma_tf32(sacc[nt], af0, bf0);
                mma_tf32(sacc[nt], af1, bf1);
            }
        }

        // ---- online softmax (rows g, g+8), log2 domain ----
        float rm0 = -1e30f, rm1 = -1e30f;
#pragma unroll
        for (int nt = 0; nt < 8; nt++) {
            rm0 = fmaxf(rm0, fmaxf(sacc[nt][0], sacc[nt][1]));
            rm1 = fmaxf(rm1, fmaxf(sacc[nt][2], sacc[nt][3]));
        }
        rm0 = fmaxf(rm0, __shfl_xor_sync(0xffffffffu, rm0, 1));
        rm0 = fmaxf(rm0, __shfl_xor_sync(0xffffffffu, rm0, 2));
        rm1 = fmaxf(rm1, __shfl_xor_sync(0xffffffffu, rm1, 1));
        rm1 = fmaxf(rm1, __shfl_xor_sync(0xffffffffu, rm1, 2));

        const float mn0 = fmaxf(M0, rm0);
        const float mn1 = fmaxf(M1, rm1);
        const float fac0 = ex2f(M0 - mn0);
        const float fac1 = ex2f(M1 - mn1);
        float rs0 = 0.0f, rs1 = 0.0f;
#pragma unroll
        for (int nt = 0; nt < 8; nt++) {
            float p0 = ex2f(sacc[nt][0] - mn0);
            float p1 = ex2f(sacc[nt][1] - mn0);
            float p2 = ex2f(sacc[nt][2] - mn1);
            float p3 = ex2f(sacc[nt][3] - mn1);
            rs0 += p0 + p1;
            rs1 += p2 + p3;
            uint2 u0, u1;
            u0.x = to_tf32(p0); u0.y = to_tf32(p1);
            u1.x = to_tf32(p2); u1.y = to_tf32(p3);
            // P tile: A-layout, k = j
            *(uint2*)(smc + nt * PT_KSB + (wrow + g) * 48 + tig * 8) = u0;
            *(uint2*)(smc + nt * PT_KSB + (wrow + g + 8) * 48 + tig * 8) = u1;
        }
        rs0 += __shfl_xor_sync(0xffffffffu, rs0, 1);
        rs0 += __shfl_xor_sync(0xffffffffu, rs0, 2);
        rs1 += __shfl_xor_sync(0xffffffffu, rs1, 1);
        rs1 += __shfl_xor_sync(0xffffffffu, rs1, 2);
        L0 = L0 * fac0 + rs0;
        L1 = L1 * fac1 + rs1;
        M0 = mn0; M1 = mn1;
#pragma unroll
        for (int nt = 0; nt < 8; nt++) {
            oacc[nt][0] *= fac0; oacc[nt][1] *= fac0;
            oacc[nt][2] *= fac1; oacc[nt][3] *= fac1;
        }
        __syncwarp();     // P rows are per-warp

        // ---- O += P @ V ----
#pragma unroll
        for (int ks2 = 0; ks2 < 4; ks2++) {
            uint4 pf0, pf1;
            ldsm_x4(pf0, smem_s + (2 * ks2)     * PT_KSB + wrow * 48 + a_ld_lane);
            ldsm_x4(pf1, smem_s + (2 * ks2 + 1) * PT_KSB + wrow * 48 + a_ld_lane);
            const uint32_t pa0[4] = {pf0.x, pf0.y, pf0.z, pf0.w};
            const uint32_t pa1[4] = {pf1.x, pf1.y, pf1.z, pf1.w};
            const uint32_t vbase = smem_s + VT2_OFF + ks2 * 2 * ATILE_KSB;
#pragma unroll
            for (int nt = 0; nt < 8; nt++) {
                uint4 bvv;
                ldsm_x4(bvv, vbase + nt * 8 * 48 + b_ld4);
                const uint32_t bf0[2] = {bvv.x, bvv.y};
                const uint32_t bf1[2] = {bvv.z, bvv.w};
                mma_tf32(oacc[nt], pa0, bf0);
                mma_tf32(oacc[nt], pa1, bf1);
            }
        }
        __syncwarp();     // done reading P before next overwrite
    }

    // Finalize: divide by L, write ctx [B,S,D]  (D col = h*64 + d)
    const int b = bh >> 4;
    const int h = bh & 15;
    const float inv0 = 1.0f / L0;
    const float inv1 = 1.0f / L1;
    const int sr0 = qt * 128 + wrow + g;
    float* out0 = g_ctx + ((size_t)(b * NS + sr0))     * ND + h * HD;
    float* out1 = g_ctx + ((size_t)(b * NS + sr0 + 8)) * ND + h * HD;
#pragma unroll
    for (int nt = 0; nt < 8; nt++) {
        const int c = nt * 8 + 2 * tig;
        *(float2*)(out0 + c) = make_float2(oacc[nt][0] * inv0, oacc[nt][1] * inv0);
        *(float2*)(out1 + c) = make_float2(oacc[nt][2] * inv1, oacc[nt][3] * inv1);
    }
}

// ---------------------------------------------------------------------------
extern "C" void kernel_launch(void* const* d_in, const int* in_sizes, int n_in,
                              void* d_out, int out_size)
{
    const float* in_q = (const float*)d_in[0];
    const float* enc  = (const float*)d_in[1];
    const float* Wqk  = (const float*)d_in[2];
    const float* bqk  = (const float*)d_in[3];
    const float* Wv   = (const float*)d_in[4];
    const float* bv   = (const float*)d_in[5];
    const float* Wo   = (const float*)d_in[6];
    const float* bo   = (const float*)d_in[7];
    float* out = (float*)d_out;

    cudaFuncSetAttribute(gemm_tf32<0>,
                         cudaFuncAttributeMaxDynamicSharedMemorySize,
                         GEMM_SMEM_BYTES);
    cudaFuncSetAttribute(gemm_tf32<1>,
                         cudaFuncAttributeMaxDynamicSharedMemorySize,
                         GEMM_SMEM_BYTES);
    cudaFuncSetAttribute(gemm_tf32<2>,
                         cudaFuncAttributeMaxDynamicSharedMemorySize,
                         GEMM_SMEM_BYTES);
    cudaFuncSetAttribute(attn_kernel,
                         cudaFuncAttributeMaxDynamicSharedMemorySize,
                         ATTN_SMEM_BYTES);

    gemm_tf32<0><<<dim3(2048 / 128, 8192 / 128), 256, GEMM_SMEM_BYTES>>>(enc, Wqk, bqk, nullptr, 1024, 2048);
    gemm_tf32<1><<<dim3(1024 / 128, 8192 / 128), 256, GEMM_SMEM_BYTES>>>(in_q, Wv, bv, nullptr, 1024, 1024);
    attn_kernel<<<dim3(8, 128), 256, ATTN_SMEM_BYTES>>>();
    gemm_tf32<2><<<dim3(1024 / 128, 8192 / 128), 256, GEMM_SMEM_BYTES>>>(nullptr, Wo, bo, out, 1024, 1024);
}